// round 4
// baseline (speedup 1.0000x reference)
#include <cuda_runtime.h>

#define VD 48
#define NC 16
#define G3 (VD*VD*VD)            // 110592 groups
#define DTOT (G3*VD)             // 5308416 cross-feature dims
#define D4 (DTOT/4)              // 1327104 float4 per class row
#define GX 162                   // blocks per class (GX*TPB divides D4; GX*TPB % 12 == 0)
#define TPB 256
#define STRIDE (GX*TPB)          // 41472
#define ITERS (D4/STRIDE)        // 32
#define GSTRIDE (STRIDE/12)      // 3456

__device__ float g_p012[G3];
__device__ float g_part[NC*GX];

// Precompute p012[g] = x0[i0]*x1[i1]*x2[i2], g = i0*2304 + i1*48 + i2
__global__ void k_p012(const float* __restrict__ x) {
    int g = blockIdx.x * blockDim.x + threadIdx.x;
    if (g >= G3) return;
    int i2 = g % VD;
    int t  = g / VD;
    int i1 = t % VD;
    int i0 = t / VD;
    g_p012[g] = x[i0] * x[VD + i1] * x[2*VD + i2];
}

// Main streaming GEMV over W (340 MB, read once).
__global__ void __launch_bounds__(TPB) k_main(const float* __restrict__ W,
                                              const float* __restrict__ x) {
    const int c  = blockIdx.y;
    const int t4 = blockIdx.x * TPB + threadIdx.x;      // [0, STRIDE)
    const int m  = t4 % 12;                              // loop-invariant (STRIDE % 12 == 0)
    int g        = t4 / 12;

    // x3 segment for this thread's phase, held in registers for the whole loop
    const float4 x3 = reinterpret_cast<const float4*>(x + 3*VD)[m];

    const float4* Wp = reinterpret_cast<const float4*>(W) + (size_t)c * D4 + t4;

    float acc = 0.f;
#pragma unroll 4
    for (int k = 0; k < ITERS; ++k) {
        float4 w = __ldcs(Wp);                // streaming: don't thrash L2 (p012 lives there)
        float  p = __ldg(&g_p012[g]);
        float dot = w.x*x3.x + w.y*x3.y + w.z*x3.z + w.w*x3.w;
        acc += p * dot;
        Wp += STRIDE;
        g  += GSTRIDE;
    }

    // Deterministic block reduction
    #pragma unroll
    for (int off = 16; off; off >>= 1)
        acc += __shfl_down_sync(0xFFFFFFFFu, acc, off);

    __shared__ float sred[TPB/32];
    if ((threadIdx.x & 31) == 0) sred[threadIdx.x >> 5] = acc;
    __syncthreads();
    if (threadIdx.x < TPB/32) {
        float v = sred[threadIdx.x];
        #pragma unroll
        for (int off = (TPB/64); off; off >>= 1)
            v += __shfl_down_sync(0xFFu, v, off);
        if (threadIdx.x == 0) g_part[c * GX + blockIdx.x] = v;
    }
}

// Final: reduce GX partials per class, add bias, relu. One block, 16 warps.
__global__ void k_final(const float* __restrict__ b, float* __restrict__ out) {
    int c    = threadIdx.x >> 5;     // class = warp id (16 warps)
    int lane = threadIdx.x & 31;
    float s = 0.f;
    for (int i = lane; i < GX; i += 32) s += g_part[c * GX + i];
    #pragma unroll
    for (int off = 16; off; off >>= 1)
        s += __shfl_down_sync(0xFFFFFFFFu, s, off);
    if (lane == 0) {
        float v = s + b[c];
        out[c] = v > 0.f ? v : 0.f;
    }
}

extern "C" void kernel_launch(void* const* d_in, const int* in_sizes, int n_in,
                              void* d_out, int out_size) {
    // Identify inputs robustly by element count: x=192, W=16*D, b=16
    const float* x = nullptr; const float* W = nullptr; const float* b = nullptr;
    for (int i = 0; i < n_in; ++i) {
        if      (in_sizes[i] == 4*VD)          x = (const float*)d_in[i];
        else if (in_sizes[i] == NC*DTOT)       W = (const float*)d_in[i];
        else if (in_sizes[i] == NC)            b = (const float*)d_in[i];
    }

    k_p012<<<(G3 + 255)/256, 256>>>(x);
    dim3 grid(GX, NC);
    k_main<<<grid, TPB>>>(W, x);
    k_final<<<1, 512>>>(b, (float*)d_out);
}

// round 6
// speedup vs baseline: 1.1141x; 1.1141x over previous
#include <cuda_runtime.h>

#define VD 48
#define NC 16
#define G3 (VD*VD*VD)            // 110592 groups
#define DTOT (G3*VD)             // 5308416 cross-feature dims
#define D4 (DTOT/4)              // 1327104 float4 per class row
#define GX 162                   // blocks per class
#define TPB 256
#define STRIDE (GX*TPB)          // 41472 (divisible by 12)
#define ITERS (D4/STRIDE)        // 32
#define Q01N (VD*VD)             // 2304

__device__ float g_part[NC*GX];

// Main streaming GEMV over W (340 MB, read once). p012 factored as
// q01[i0*48+i1] (shared) * x2[i2] (folded into x3 registers).
__global__ void __launch_bounds__(TPB) k_main(const float* __restrict__ W,
                                              const float* __restrict__ x) {
    __shared__ float q01[Q01N];          // x0 (x) x1 outer product, 9 KB
    __shared__ float sred[TPB/32];

    // Build q01 cooperatively: 2304 / 256 = 9 iterations
    #pragma unroll
    for (int idx = threadIdx.x; idx < Q01N; idx += TPB)
        q01[idx] = __ldg(&x[idx / VD]) * __ldg(&x[VD + idx % VD]);
    __syncthreads();

    const int c  = blockIdx.y;
    const int t4 = blockIdx.x * TPB + threadIdx.x;      // [0, STRIDE)
    const int m  = t4 % 12;                              // i3 segment (invariant)
    const int g0 = t4 / 12;                              // [0, 3456)
    const int i2 = g0 % VD;                              // invariant: GSTRIDE % 48 == 0
    int t01      = g0 / VD;                              // [0,72), += 72/iter, max 2303

    // x3 float4 for this thread's phase, pre-scaled by x2[i2]
    const float c2 = __ldg(&x[2*VD + i2]);
    float4 x3 = reinterpret_cast<const float4*>(x + 3*VD)[m];
    x3.x *= c2; x3.y *= c2; x3.z *= c2; x3.w *= c2;

    const float4* Wp = reinterpret_cast<const float4*>(W) + (size_t)c * D4 + t4;

    float acc = 0.f;
#pragma unroll 4
    for (int k = 0; k < ITERS; ++k) {
        float4 w = __ldcs(Wp);           // streaming: W has zero reuse
        float  p = q01[t01];             // broadcast LDS (<=2 addrs/warp)
        acc += p * (w.x*x3.x + w.y*x3.y + w.z*x3.z + w.w*x3.w);
        Wp  += STRIDE;
        t01 += 72;
    }

    // Deterministic block reduction
    #pragma unroll
    for (int off = 16; off; off >>= 1)
        acc += __shfl_down_sync(0xFFFFFFFFu, acc, off);

    if ((threadIdx.x & 31) == 0) sred[threadIdx.x >> 5] = acc;
    __syncthreads();
    if (threadIdx.x < TPB/32) {
        float v = sred[threadIdx.x];
        #pragma unroll
        for (int off = (TPB/64); off; off >>= 1)
            v += __shfl_down_sync(0xFFu, v, off);
        if (threadIdx.x == 0) g_part[c * GX + blockIdx.x] = v;
    }
}

// Final: reduce GX partials per class, add bias, relu. One block, 16 warps.
__global__ void k_final(const float* __restrict__ b, float* __restrict__ out) {
    int c    = threadIdx.x >> 5;
    int lane = threadIdx.x & 31;
    float s = 0.f;
    for (int i = lane; i < GX; i += 32) s += g_part[c * GX + i];
    #pragma unroll
    for (int off = 16; off; off >>= 1)
        s += __shfl_down_sync(0xFFFFFFFFu, s, off);
    if (lane == 0) {
        float v = s + b[c];
        out[c] = v > 0.f ? v : 0.f;
    }
}

extern "C" void kernel_launch(void* const* d_in, const int* in_sizes, int n_in,
                              void* d_out, int out_size) {
    const float* x = nullptr; const float* W = nullptr; const float* b = nullptr;
    for (int i = 0; i < n_in; ++i) {
        if      (in_sizes[i] == 4*VD)    x = (const float*)d_in[i];
        else if (in_sizes[i] == NC*DTOT) W = (const float*)d_in[i];
        else if (in_sizes[i] == NC)      b = (const float*)d_in[i];
    }

    dim3 grid(GX, NC);
    k_main<<<grid, TPB>>>(W, x);
    k_final<<<1, 512>>>(b, (float*)d_out);
}